// round 5
// baseline (speedup 1.0000x reference)
#include <cuda_runtime.h>

#define NB 16
#define NN 4096
#define ND 64
#define NPOINT 1024
#define NSAMP 32
#define C0 67
#define O0 64
#define O1 64
#define O2 128
#define OUT_XYZ (NB*NPOINT*3)
#define GPB 8

// smem strides
#define S0 67   // W0 row stride
#define S1 65   // W1 row stride (odd -> conflict-free)
#define SH 68   // activation row stride
#define SG 132  // maxpool scratch stride

// -------- device scratch (no allocations allowed) --------
__device__ int   g_fps[NB * NPOINT];
__device__ int   g_grp[NB * NPOINT * NSAMP];
__device__ float g_W0f[O0 * C0];
__device__ float g_b0f[O0];
__device__ float g_W1f[O1 * O0];
__device__ float g_b1f[O1];
__device__ __align__(16) float g_W2t[O1 * O2];   // transposed [c][o]
__device__ float g_b2f[O2];

// ===================== BN fold =====================
__global__ void fold_kernel(
    const float* __restrict__ W0, const float* __restrict__ b0, const float* __restrict__ g0,
    const float* __restrict__ be0, const float* __restrict__ m0, const float* __restrict__ v0,
    const float* __restrict__ W1, const float* __restrict__ b1, const float* __restrict__ g1,
    const float* __restrict__ be1, const float* __restrict__ m1, const float* __restrict__ v1,
    const float* __restrict__ W2, const float* __restrict__ b2, const float* __restrict__ g2,
    const float* __restrict__ be2, const float* __restrict__ m2, const float* __restrict__ v2)
{
    int t = threadIdx.x;
    int nt = blockDim.x;
    for (int e = t; e < O0 * C0; e += nt) {
        int o = e / C0;
        g_W0f[e] = W0[e] * (g0[o] * rsqrtf(v0[o] + 1e-5f));
    }
    for (int e = t; e < O1 * O0; e += nt) {
        int o = e >> 6;
        g_W1f[e] = W1[e] * (g1[o] * rsqrtf(v1[o] + 1e-5f));
    }
    // W2 transposed: g_W2t[c*128 + o] = W2[o*64 + c] * scale(o)
    for (int e = t; e < O2 * O1; e += nt) {
        int c = e >> 7;          // 0..63
        int o = e & 127;         // 0..127
        g_W2t[e] = W2[o * O1 + c] * (g2[o] * rsqrtf(v2[o] + 1e-5f));
    }
    for (int o = t; o < O0; o += nt)
        g_b0f[o] = (b0[o] - m0[o]) * (g0[o] * rsqrtf(v0[o] + 1e-5f)) + be0[o];
    for (int o = t; o < O1; o += nt)
        g_b1f[o] = (b1[o] - m1[o]) * (g1[o] * rsqrtf(v1[o] + 1e-5f)) + be1[o];
    for (int o = t; o < O2; o += nt)
        g_b2f[o] = (b2[o] - m2[o]) * (g2[o] * rsqrtf(v2[o] + 1e-5f)) + be2[o];
}

// ===================== FPS (register-resident points, no big smem) =====================
// Each thread owns 8 points (coords in registers). The argmax reduction carries
// the winning point's coordinates so the next centroid needs no memory lookup.
__global__ __launch_bounds__(512) void fps_kernel(const float* __restrict__ xyz)
{
    __shared__ float swv[16];
    __shared__ int   swi[16];
    __shared__ float swx[16], swy[16], swz[16];
    __shared__ float scx, scy, scz;
    __shared__ int   sfar;

    int b = blockIdx.x;
    int t = threadIdx.x;
    const float* p = xyz + (size_t)b * NN * 3;

    float px[8], py[8], pz[8], dl[8];
#pragma unroll
    for (int i = 0; i < 8; i++) {
        int pi = t + i * 512;
        px[i] = p[3 * pi + 0];
        py[i] = p[3 * pi + 1];
        pz[i] = p[3 * pi + 2];
        dl[i] = 1e10f;
    }
    if (t == 0) {
        g_fps[b * NPOINT] = 0;
        scx = p[0]; scy = p[1]; scz = p[2];
    }
    __syncthreads();

    float cx = scx, cy = scy, cz = scz;
    for (int it = 1; it < NPOINT; it++) {
        float bv = -1.0f, bx = 0.f, by = 0.f, bz = 0.f;
        int bi = 0;
#pragma unroll
        for (int i = 0; i < 8; i++) {
            int pi = t + i * 512;
            float dx = px[i] - cx;
            float dy = py[i] - cy;
            float dz = pz[i] - cz;
            // fma-contracted form (matches default XLA codegen):
            float d = fmaf(dz, dz, fmaf(dy, dy, __fmul_rn(dx, dx)));
            float dn = fminf(dl[i], d);
            dl[i] = dn;
            if (dn > bv) { bv = dn; bi = pi; bx = px[i]; by = py[i]; bz = pz[i]; }
        }
        // warp argmax (val desc, idx asc on ties), carrying coords
#pragma unroll
        for (int off = 16; off > 0; off >>= 1) {
            float ov = __shfl_down_sync(0xffffffffu, bv, off);
            int   oi = __shfl_down_sync(0xffffffffu, bi, off);
            float ox = __shfl_down_sync(0xffffffffu, bx, off);
            float oy = __shfl_down_sync(0xffffffffu, by, off);
            float oz = __shfl_down_sync(0xffffffffu, bz, off);
            if (ov > bv || (ov == bv && oi < bi)) {
                bv = ov; bi = oi; bx = ox; by = oy; bz = oz;
            }
        }
        if ((t & 31) == 0) {
            int w = t >> 5;
            swv[w] = bv; swi[w] = bi; swx[w] = bx; swy[w] = by; swz[w] = bz;
        }
        __syncthreads();
        if (t < 32) {
            bv = (t < 16) ? swv[t] : -2.0f;
            bi = (t < 16) ? swi[t] : 0x7fffffff;
            bx = (t < 16) ? swx[t] : 0.f;
            by = (t < 16) ? swy[t] : 0.f;
            bz = (t < 16) ? swz[t] : 0.f;
#pragma unroll
            for (int off = 8; off > 0; off >>= 1) {
                float ov = __shfl_down_sync(0xffffffffu, bv, off);
                int   oi = __shfl_down_sync(0xffffffffu, bi, off);
                float ox = __shfl_down_sync(0xffffffffu, bx, off);
                float oy = __shfl_down_sync(0xffffffffu, by, off);
                float oz = __shfl_down_sync(0xffffffffu, bz, off);
                if (ov > bv || (ov == bv && oi < bi)) {
                    bv = ov; bi = oi; bx = ox; by = oy; bz = oz;
                }
            }
            if (t == 0) {
                sfar = bi; scx = bx; scy = by; scz = bz;
                g_fps[b * NPOINT + it] = bi;
            }
        }
        __syncthreads();
        cx = scx; cy = scy; cz = scz;
    }
}

// ===================== ball query (+new_xyz write) =====================
__global__ __launch_bounds__(256) void ballquery_kernel(const float* __restrict__ xyz,
                                                        float* __restrict__ out)
{
    int gw = (blockIdx.x * 256 + threadIdx.x) >> 5;
    int lane = threadIdx.x & 31;
    if (gw >= NB * NPOINT) return;
    int b = gw >> 10;
    const float* p = xyz + (size_t)b * NN * 3;

    int ci = g_fps[gw];
    float cx = p[3 * ci + 0];
    float cy = p[3 * ci + 1];
    float cz = p[3 * ci + 2];
    if (lane < 3) out[(size_t)gw * 3 + lane] = p[3 * ci + lane];

    float sn = fmaf(cz, cz, fmaf(cy, cy, __fmul_rn(cx, cx)));
    int* grp = g_grp + (size_t)gw * NSAMP;

    int cnt = 0;
    int first = ci;
    bool gotfirst = false;
    for (int base = 0; base < NN && cnt < NSAMP; base += 32) {
        int i = base + lane;
        float x = p[3 * i + 0], y = p[3 * i + 1], z = p[3 * i + 2];
        float sp = fmaf(z, z, fmaf(y, y, __fmul_rn(x, x)));
        float dt = fmaf(cz, z, fmaf(cy, y, __fmul_rn(cx, x)));
        float d2 = fmaf(-2.0f, dt, sn + sp);
        bool isin = !(d2 > 0.04f);
        unsigned m = __ballot_sync(0xffffffffu, isin);
        if (!gotfirst && m) { first = base + __ffs(m) - 1; gotfirst = true; }
        int pos = cnt + __popc(m & ((1u << lane) - 1u));
        if (isin && pos < NSAMP) grp[pos] = i;
        cnt += __popc(m);
    }
    if (cnt < NSAMP) {
        int p0 = cnt + lane;
        if (p0 < NSAMP) grp[p0] = first;
    }
}

// ===================== fused gather + MLP(3) + maxpool =====================
// All static smem (~44 KB < 48 KB) -> no attribute calls, graph-capturable.
__global__ __launch_bounds__(128) void mlp_kernel(const float* __restrict__ xyz,
                                                  const float* __restrict__ pts,
                                                  float* __restrict__ out)
{
    __shared__ float sW0[O0 * S0];     // 4288 floats
    __shared__ float sW1[O1 * S1];     // 4160
    __shared__ float sb[256 + O2];     // [0,64)=b0 [64,128)=b1 [128,256)=b2
    __shared__ float hin[NSAMP * SH];  // 2176 ; reused as gmax[8][SG]
    __shared__ int   sidx[NSAMP];
    __shared__ float scen[3];

    int t = threadIdx.x;
    int kt = t >> 4;   // 0..7  (k = kt + 8*i)
    int ot = t & 15;   // 0..15

    for (int e = t; e < O0 * C0; e += 128) sW0[e] = g_W0f[e];
    for (int e = t; e < O1 * O0; e += 128) sW1[(e >> 6) * S1 + (e & 63)] = g_W1f[e];
    if (t < 64)       sb[t] = g_b0f[t];
    else              sb[t] = g_b1f[t - 64];
    for (int e = t; e < O2; e += 128) sb[128 + e] = g_b2f[e];
    __syncthreads();

    for (int g = 0; g < GPB; g++) {
        int gw = blockIdx.x * GPB + g;
        int b = gw >> 10;
        const float* pxyz = xyz + (size_t)b * NN * 3;
        const float* ppts = pts + (size_t)b * NN * ND;

        if (t < NSAMP) sidx[t] = g_grp[(size_t)gw * NSAMP + t];
        if (t < 3)     scen[t] = out[(size_t)gw * 3 + t];
        __syncthreads();

        // gather: hin[k][c] = c<3 ? xyz[id][c]-cen[c] : points[id][c-3]
        for (int e = t; e < NSAMP * C0; e += 128) {
            int k = e / C0;
            int c = e - k * C0;
            int id = sidx[k];
            float v;
            if (c < 3) v = pxyz[3 * id + c] - scen[c];
            else       v = ppts[(size_t)id * ND + (c - 3)];
            hin[k * SH + c] = v;
        }
        __syncthreads();

        // ---- Layer 0: [32,67] x W0[64,67]^T ; regs -> writeback into hin ----
        {
            float acc[4][4] = {};
            for (int c = 0; c < C0; c++) {
                float a[4], w[4];
#pragma unroll
                for (int i = 0; i < 4; i++) a[i] = hin[(kt + 8 * i) * SH + c];
#pragma unroll
                for (int j = 0; j < 4; j++) w[j] = sW0[(ot + 16 * j) * S0 + c];
#pragma unroll
                for (int i = 0; i < 4; i++)
#pragma unroll
                    for (int j = 0; j < 4; j++) acc[i][j] = fmaf(a[i], w[j], acc[i][j]);
            }
            __syncthreads();   // all reads of hin done
#pragma unroll
            for (int i = 0; i < 4; i++)
#pragma unroll
                for (int j = 0; j < 4; j++) {
                    int k = kt + 8 * i, o = ot + 16 * j;
                    hin[k * SH + o] = fmaxf(acc[i][j] + sb[o], 0.0f);
                }
        }
        __syncthreads();

        // ---- Layer 1: [32,64] x W1[64,64]^T ; regs -> writeback into hin ----
        {
            float acc[4][4] = {};
            for (int c = 0; c < O0; c++) {
                float a[4], w[4];
#pragma unroll
                for (int i = 0; i < 4; i++) a[i] = hin[(kt + 8 * i) * SH + c];
#pragma unroll
                for (int j = 0; j < 4; j++) w[j] = sW1[(ot + 16 * j) * S1 + c];
#pragma unroll
                for (int i = 0; i < 4; i++)
#pragma unroll
                    for (int j = 0; j < 4; j++) acc[i][j] = fmaf(a[i], w[j], acc[i][j]);
            }
            __syncthreads();
#pragma unroll
            for (int i = 0; i < 4; i++)
#pragma unroll
                for (int j = 0; j < 4; j++) {
                    int k = kt + 8 * i, o = ot + 16 * j;
                    hin[k * SH + o] = fmaxf(acc[i][j] + sb[64 + o], 0.0f);
                }
        }
        __syncthreads();

        // ---- Layer 2: [32,64] x W2t (global, transposed, float4, L1-resident),
        //      then max over k ----
        {
            float acc[4][8] = {};
            const float4* W2v = reinterpret_cast<const float4*>(g_W2t);
            for (int c = 0; c < O1; c++) {
                float a[4];
#pragma unroll
                for (int i = 0; i < 4; i++) a[i] = hin[(kt + 8 * i) * SH + c];
                // o = ot*8 + j  (j = 0..7); two contiguous float4 loads
                float4 w0 = __ldg(&W2v[c * 32 + ot * 2 + 0]);
                float4 w1 = __ldg(&W2v[c * 32 + ot * 2 + 1]);
                float w[8] = {w0.x, w0.y, w0.z, w0.w, w1.x, w1.y, w1.z, w1.w};
#pragma unroll
                for (int i = 0; i < 4; i++)
#pragma unroll
                    for (int j = 0; j < 8; j++) acc[i][j] = fmaf(a[i], w[j], acc[i][j]);
            }
            __syncthreads();   // hin reads done; reuse as gmax[8][SG]
            float* gmax = hin;
#pragma unroll
            for (int j = 0; j < 8; j++) {
                int o = ot * 8 + j;
                float bias = sb[128 + o];
                float pm = fmaxf(acc[0][j] + bias, 0.0f);
#pragma unroll
                for (int i = 1; i < 4; i++)
                    pm = fmaxf(pm, fmaxf(acc[i][j] + bias, 0.0f));
                gmax[kt * SG + o] = pm;
            }
            __syncthreads();
            // final max over 8 kt slices; thread t handles channel o = t
            float mx = gmax[t];
#pragma unroll
            for (int q = 1; q < 8; q++) mx = fmaxf(mx, gmax[q * SG + t]);
            out[OUT_XYZ + (size_t)gw * O2 + t] = mx;
        }
        __syncthreads();   // protect hin/sidx before next group's writes
    }
}

// ===================== launch =====================
extern "C" void kernel_launch(void* const* d_in, const int* in_sizes, int n_in,
                              void* d_out, int out_size)
{
    const float* xyz = (const float*)d_in[0];
    const float* pts = (const float*)d_in[1];
    const float* W0  = (const float*)d_in[2];
    const float* b0  = (const float*)d_in[3];
    const float* g0  = (const float*)d_in[4];
    const float* be0 = (const float*)d_in[5];
    const float* m0  = (const float*)d_in[6];
    const float* v0  = (const float*)d_in[7];
    const float* W1  = (const float*)d_in[8];
    const float* b1  = (const float*)d_in[9];
    const float* g1  = (const float*)d_in[10];
    const float* be1 = (const float*)d_in[11];
    const float* m1  = (const float*)d_in[12];
    const float* v1  = (const float*)d_in[13];
    const float* W2  = (const float*)d_in[14];
    const float* b2  = (const float*)d_in[15];
    const float* g2  = (const float*)d_in[16];
    const float* be2 = (const float*)d_in[17];
    const float* m2  = (const float*)d_in[18];
    const float* v2  = (const float*)d_in[19];
    float* out = (float*)d_out;

    // Kernel launches ONLY — graph-capturable. No dynamic smem anywhere.
    fold_kernel<<<1, 256>>>(W0, b0, g0, be0, m0, v0,
                            W1, b1, g1, be1, m1, v1,
                            W2, b2, g2, be2, m2, v2);
    fps_kernel<<<NB, 512>>>(xyz);
    ballquery_kernel<<<(NB * NPOINT) / 8, 256>>>(xyz, out);
    mlp_kernel<<<(NB * NPOINT) / GPB, 128>>>(xyz, pts, out);
}

// round 7
// speedup vs baseline: 1.0223x; 1.0223x over previous
#include <cuda_runtime.h>

#define NB 16
#define NN 4096
#define ND 64
#define NPOINT 1024
#define NSAMP 32
#define C0 67
#define O0 64
#define O1 64
#define O2 128
#define OUT_XYZ (NB*NPOINT*3)
#define GPB 8

#define SK 36    // activation row stride (mult of 4 for float4)
#define SG 132   // maxpool scratch stride

// -------- device scratch (no allocations allowed) --------
__device__ int   g_fps[NB * NPOINT];
__device__ int   g_grp[NB * NPOINT * NSAMP];
__device__ __align__(16) float g_W0t[C0 * O0];   // [c][o]
__device__ __align__(16) float g_W1t[O0 * O1];   // [c][o]
__device__ __align__(16) float g_W2t[O1 * O2];   // [c][o]
__device__ float g_b0f[O0];
__device__ float g_b1f[O1];
__device__ float g_b2f[O2];

// ---- packed f32x2 helpers (bit-identical rn ops, 2 points/instr) ----
#define PACK2(out, lo, hi) \
    asm("mov.b64 %0, {%1, %2};" : "=l"(out) : "f"(lo), "f"(hi))
#define UNPACK2(lo, hi, in) \
    asm("mov.b64 {%0, %1}, %2;" : "=f"(lo), "=f"(hi) : "l"(in))
#define ADD2(out, a, b) \
    asm("add.rn.f32x2 %0, %1, %2;" : "=l"(out) : "l"(a), "l"(b))
#define MUL2(out, a, b) \
    asm("mul.rn.f32x2 %0, %1, %2;" : "=l"(out) : "l"(a), "l"(b))
#define FMA2(out, a, b, c) \
    asm("fma.rn.f32x2 %0, %1, %2, %3;" : "=l"(out) : "l"(a), "l"(b), "l"(c))

// ===================== BN fold (writes transposed weights) =====================
__global__ void fold_kernel(
    const float* __restrict__ W0, const float* __restrict__ b0, const float* __restrict__ g0,
    const float* __restrict__ be0, const float* __restrict__ m0, const float* __restrict__ v0,
    const float* __restrict__ W1, const float* __restrict__ b1, const float* __restrict__ g1,
    const float* __restrict__ be1, const float* __restrict__ m1, const float* __restrict__ v1,
    const float* __restrict__ W2, const float* __restrict__ b2, const float* __restrict__ g2,
    const float* __restrict__ be2, const float* __restrict__ m2, const float* __restrict__ v2)
{
    int t = threadIdx.x;
    int nt = blockDim.x;
    for (int e = t; e < C0 * O0; e += nt) {
        int c = e >> 6, o = e & 63;
        g_W0t[e] = W0[o * C0 + c] * (g0[o] * rsqrtf(v0[o] + 1e-5f));
    }
    for (int e = t; e < O0 * O1; e += nt) {
        int c = e >> 6, o = e & 63;
        g_W1t[e] = W1[o * O0 + c] * (g1[o] * rsqrtf(v1[o] + 1e-5f));
    }
    for (int e = t; e < O1 * O2; e += nt) {
        int c = e >> 7, o = e & 127;
        g_W2t[e] = W2[o * O1 + c] * (g2[o] * rsqrtf(v2[o] + 1e-5f));
    }
    for (int o = t; o < O0; o += nt)
        g_b0f[o] = (b0[o] - m0[o]) * (g0[o] * rsqrtf(v0[o] + 1e-5f)) + be0[o];
    for (int o = t; o < O1; o += nt)
        g_b1f[o] = (b1[o] - m1[o]) * (g1[o] * rsqrtf(v1[o] + 1e-5f)) + be1[o];
    for (int o = t; o < O2; o += nt)
        g_b2f[o] = (b2[o] - m2[o]) * (g2[o] * rsqrtf(v2[o] + 1e-5f)) + be2[o];
}

// ===================== FPS =====================
// Packed u64 argmax key, single barrier/iter via triple-buffered atomicMax slot,
// f32x2 packed distance math (bit-identical to scalar rn ops).
__global__ __launch_bounds__(512) void fps_kernel(const float* __restrict__ xyz)
{
    __shared__ unsigned long long sky[3];

    int b = blockIdx.x;
    int t = threadIdx.x;
    const float* p = xyz + (size_t)b * NN * 3;

    float dl[8];
    unsigned long long px2[4], py2[4], pz2[4];
#pragma unroll
    for (int j = 0; j < 4; j++) {
        int p0 = t + (2 * j) * 512;
        int p1 = t + (2 * j + 1) * 512;
        float x0 = p[3 * p0], y0 = p[3 * p0 + 1], z0 = p[3 * p0 + 2];
        float x1 = p[3 * p1], y1 = p[3 * p1 + 1], z1 = p[3 * p1 + 2];
        PACK2(px2[j], x0, x1);
        PACK2(py2[j], y0, y1);
        PACK2(pz2[j], z0, z1);
        dl[2 * j] = 1e10f;
        dl[2 * j + 1] = 1e10f;
    }
    if (t == 0) {
        g_fps[b * NPOINT] = 0;
        sky[0] = 0ULL; sky[1] = 0ULL; sky[2] = 0ULL;
    }
    __syncthreads();

    float cx = p[0], cy = p[1], cz = p[2];
    int s = 1;   // slot for this iteration
    for (int it = 1; it < NPOINT; it++) {
        unsigned long long ncx2, ncy2, ncz2;
        {
            float nx = -cx, ny = -cy, nz = -cz;
            PACK2(ncx2, nx, nx);
            PACK2(ncy2, ny, ny);
            PACK2(ncz2, nz, nz);
        }
        float bv = -1.0f;
        int bi = 0;
#pragma unroll
        for (int j = 0; j < 4; j++) {
            unsigned long long dxp, dyp, dzp, dp;
            ADD2(dxp, px2[j], ncx2);          // x - cx  (== x + (-cx), exact)
            ADD2(dyp, py2[j], ncy2);
            ADD2(dzp, pz2[j], ncz2);
            MUL2(dp, dxp, dxp);               // dx*dx
            FMA2(dp, dyp, dyp, dp);           // + dy*dy
            FMA2(dp, dzp, dzp, dp);           // + dz*dz
            float d0, d1;
            UNPACK2(d0, d1, dp);
            float dn0 = fminf(dl[2 * j], d0);
            dl[2 * j] = dn0;
            if (dn0 > bv) { bv = dn0; bi = t + (2 * j) * 512; }
            float dn1 = fminf(dl[2 * j + 1], d1);
            dl[2 * j + 1] = dn1;
            if (dn1 > bv) { bv = dn1; bi = t + (2 * j + 1) * 512; }
        }
        // pack: value bits (nonneg float -> monotonic u32) | (4095 - idx)
        unsigned long long key =
            ((unsigned long long)__float_as_uint(bv) << 12) |
            (unsigned)(4095 - bi);
#pragma unroll
        for (int off = 16; off > 0; off >>= 1) {
            unsigned long long ok = __shfl_down_sync(0xffffffffu, key, off);
            if (ok > key) key = ok;
        }
        int nxt = (s == 2) ? 0 : s + 1;
        if ((t & 31) == 0) atomicMax(&sky[s], key);
        if (t == 0) sky[nxt] = 0ULL;   // readers of sky[nxt] finished before the PREVIOUS barrier
        __syncthreads();
        unsigned long long wk = sky[s];
        int idx = 4095 - (int)(wk & 0xFFFu);
        cx = p[3 * idx]; cy = p[3 * idx + 1]; cz = p[3 * idx + 2];  // uniform L1-hit
        if (t == 0) g_fps[b * NPOINT + it] = idx;
        s = nxt;
    }
}

// ===================== ball query (+new_xyz write) =====================
__global__ __launch_bounds__(256) void ballquery_kernel(const float* __restrict__ xyz,
                                                        float* __restrict__ out)
{
    int gw = (blockIdx.x * 256 + threadIdx.x) >> 5;
    int lane = threadIdx.x & 31;
    if (gw >= NB * NPOINT) return;
    int b = gw >> 10;
    const float* p = xyz + (size_t)b * NN * 3;

    int ci = g_fps[gw];
    float cx = p[3 * ci + 0];
    float cy = p[3 * ci + 1];
    float cz = p[3 * ci + 2];
    if (lane < 3) out[(size_t)gw * 3 + lane] = p[3 * ci + lane];

    float sn = fmaf(cz, cz, fmaf(cy, cy, __fmul_rn(cx, cx)));
    int* grp = g_grp + (size_t)gw * NSAMP;

    int cnt = 0;
    int first = ci;
    bool gotfirst = false;
    for (int base = 0; base < NN && cnt < NSAMP; base += 32) {
        int i = base + lane;
        float x = p[3 * i + 0], y = p[3 * i + 1], z = p[3 * i + 2];
        float sp = fmaf(z, z, fmaf(y, y, __fmul_rn(x, x)));
        float dt = fmaf(cz, z, fmaf(cy, y, __fmul_rn(cx, x)));
        float d2 = fmaf(-2.0f, dt, sn + sp);
        bool isin = !(d2 > 0.04f);
        unsigned m = __ballot_sync(0xffffffffu, isin);
        if (!gotfirst && m) { first = base + __ffs(m) - 1; gotfirst = true; }
        int pos = cnt + __popc(m & ((1u << lane) - 1u));
        if (isin && pos < NSAMP) grp[pos] = i;
        cnt += __popc(m);
    }
    if (cnt < NSAMP) {
        int p0 = cnt + lane;
        if (p0 < NSAMP) grp[p0] = first;
    }
}

// ===================== fused gather + MLP(3) + maxpool =====================
// Vectorized: activations [channel][k] (stride SK), weights [c][o] -> LDS.128/LDG.128.
// smem ~28 KB static; __launch_bounds__(128,6) -> 24 warps/SM.
__global__ __launch_bounds__(128, 6) void mlp_kernel(const float* __restrict__ xyz,
                                                     const float* __restrict__ pts,
                                                     float* __restrict__ out)
{
    __shared__ __align__(16) float sW0[C0 * O0];  // [c][o], 4288 floats
    __shared__ __align__(16) float A[C0 * SK];    // [chan][k], 2412; reused as gmax[8][SG]
    __shared__ float sb[256];                     // b0|b1|b2
    __shared__ int   sidx[NSAMP];
    __shared__ float scen[3];

    int t = threadIdx.x;
    int kt = t >> 4;   // k base = kt*4 (0..28)
    int ot = t & 15;   // o base = ot*4 (L0/L1) or ot*8 (L2)

    {   // contiguous float4 copy of transposed W0
        const float4* src = reinterpret_cast<const float4*>(g_W0t);
        float4* dst = reinterpret_cast<float4*>(sW0);
        for (int e = t; e < C0 * O0 / 4; e += 128) dst[e] = src[e];
    }
    if (t < 64) sb[t] = g_b0f[t];
    else        sb[t] = g_b1f[t - 64];
    for (int e = t; e < O2; e += 128) sb[128 + e] = g_b2f[e];
    __syncthreads();

    for (int g = 0; g < GPB; g++) {
        int gw = blockIdx.x * GPB + g;
        int b = gw >> 10;
        const float* pxyz = xyz + (size_t)b * NN * 3;
        const float* ppts = pts + (size_t)b * NN * ND;

        if (t < NSAMP) sidx[t] = g_grp[(size_t)gw * NSAMP + t];
        if (t < 3)     scen[t] = out[(size_t)gw * 3 + t];
        __syncthreads();

        // gather (coalesced reads), transposed write A[c][k]
        for (int e = t; e < NSAMP * C0; e += 128) {
            int k = e / C0;
            int c = e - k * C0;
            int id = sidx[k];
            float v;
            if (c < 3) v = pxyz[3 * id + c] - scen[c];
            else       v = ppts[(size_t)id * ND + (c - 3)];
            A[c * SK + k] = v;
        }
        __syncthreads();

        // ---- Layer 0: k in {kt*4+i}, o in {ot*4+j} ----
        {
            float acc[4][4] = {};
            for (int c = 0; c < C0; c++) {
                float4 av = *reinterpret_cast<const float4*>(&A[c * SK + kt * 4]);
                float4 wv = *reinterpret_cast<const float4*>(&sW0[c * O0 + ot * 4]);
                float a[4] = {av.x, av.y, av.z, av.w};
                float w[4] = {wv.x, wv.y, wv.z, wv.w};
#pragma unroll
                for (int i = 0; i < 4; i++)
#pragma unroll
                    for (int j = 0; j < 4; j++) acc[i][j] = fmaf(a[i], w[j], acc[i][j]);
            }
            __syncthreads();
#pragma unroll
            for (int j = 0; j < 4; j++) {
                int o = ot * 4 + j;
                float bias = sb[o];
                float4 r;
                r.x = fmaxf(acc[0][j] + bias, 0.0f);
                r.y = fmaxf(acc[1][j] + bias, 0.0f);
                r.z = fmaxf(acc[2][j] + bias, 0.0f);
                r.w = fmaxf(acc[3][j] + bias, 0.0f);
                *reinterpret_cast<float4*>(&A[o * SK + kt * 4]) = r;
            }
        }
        __syncthreads();

        // ---- Layer 1: W1 from global (L1-resident float4) ----
        {
            float acc[4][4] = {};
            const float4* w1v = reinterpret_cast<const float4*>(g_W1t);
            for (int c = 0; c < O0; c++) {
                float4 av = *reinterpret_cast<const float4*>(&A[c * SK + kt * 4]);
                float4 wv = __ldg(&w1v[c * 16 + ot]);
                float a[4] = {av.x, av.y, av.z, av.w};
                float w[4] = {wv.x, wv.y, wv.z, wv.w};
#pragma unroll
                for (int i = 0; i < 4; i++)
#pragma unroll
                    for (int j = 0; j < 4; j++) acc[i][j] = fmaf(a[i], w[j], acc[i][j]);
            }
            __syncthreads();
#pragma unroll
            for (int j = 0; j < 4; j++) {
                int o = ot * 4 + j;
                float bias = sb[64 + o];
                float4 r;
                r.x = fmaxf(acc[0][j] + bias, 0.0f);
                r.y = fmaxf(acc[1][j] + bias, 0.0f);
                r.z = fmaxf(acc[2][j] + bias, 0.0f);
                r.w = fmaxf(acc[3][j] + bias, 0.0f);
                *reinterpret_cast<float4*>(&A[o * SK + kt * 4]) = r;
            }
        }
        __syncthreads();

        // ---- Layer 2: o in {ot*8+j}; W2 global float4; then max over k ----
        {
            float acc[4][8] = {};
            const float4* w2v = reinterpret_cast<const float4*>(g_W2t);
            for (int c = 0; c < O1; c++) {
                float4 av = *reinterpret_cast<const float4*>(&A[c * SK + kt * 4]);
                float4 wv0 = __ldg(&w2v[c * 32 + ot * 2 + 0]);
                float4 wv1 = __ldg(&w2v[c * 32 + ot * 2 + 1]);
                float a[4] = {av.x, av.y, av.z, av.w};
                float w[8] = {wv0.x, wv0.y, wv0.z, wv0.w, wv1.x, wv1.y, wv1.z, wv1.w};
#pragma unroll
                for (int i = 0; i < 4; i++)
#pragma unroll
                    for (int j = 0; j < 8; j++) acc[i][j] = fmaf(a[i], w[j], acc[i][j]);
            }
            __syncthreads();     // A reads done; reuse as gmax[8][SG]
            float* gmax = A;
#pragma unroll
            for (int j = 0; j < 8; j++) {
                int o = ot * 8 + j;
                float bias = sb[128 + o];
                float pm = fmaxf(acc[0][j] + bias, 0.0f);
#pragma unroll
                for (int i = 1; i < 4; i++)
                    pm = fmaxf(pm, fmaxf(acc[i][j] + bias, 0.0f));
                gmax[kt * SG + o] = pm;
            }
            __syncthreads();
            float mx = gmax[t];
#pragma unroll
            for (int q = 1; q < 8; q++) mx = fmaxf(mx, gmax[q * SG + t]);
            out[OUT_XYZ + (size_t)gw * O2 + t] = mx;
        }
        __syncthreads();   // protect A/sidx before next group's writes
    }
}

// ===================== launch =====================
extern "C" void kernel_launch(void* const* d_in, const int* in_sizes, int n_in,
                              void* d_out, int out_size)
{
    const float* xyz = (const float*)d_in[0];
    const float* pts = (const float*)d_in[1];
    const float* W0  = (const float*)d_in[2];
    const float* b0  = (const float*)d_in[3];
    const float* g0  = (const float*)d_in[4];
    const float* be0 = (const float*)d_in[5];
    const float* m0  = (const float*)d_in[6];
    const float* v0  = (const float*)d_in[7];
    const float* W1  = (const float*)d_in[8];
    const float* b1  = (const float*)d_in[9];
    const float* g1  = (const float*)d_in[10];
    const float* be1 = (const float*)d_in[11];
    const float* m1  = (const float*)d_in[12];
    const float* v1  = (const float*)d_in[13];
    const float* W2  = (const float*)d_in[14];
    const float* b2  = (const float*)d_in[15];
    const float* g2  = (const float*)d_in[16];
    const float* be2 = (const float*)d_in[17];
    const float* m2  = (const float*)d_in[18];
    const float* v2  = (const float*)d_in[19];
    float* out = (float*)d_out;

    // Kernel launches ONLY — graph-capturable. No dynamic smem, no attribute calls.
    fold_kernel<<<1, 256>>>(W0, b0, g0, be0, m0, v0,
                            W1, b1, g1, be1, m1, v1,
                            W2, b2, g2, be2, m2, v2);
    fps_kernel<<<NB, 512>>>(xyz);
    ballquery_kernel<<<(NB * NPOINT) / 8, 256>>>(xyz, out);
    mlp_kernel<<<(NB * NPOINT) / GPB, 128>>>(xyz, pts, out);
}